// round 6
// baseline (speedup 1.0000x reference)
#include <cuda_runtime.h>
#include <cstdint>

#define NN 50000
#define NE 1600000

typedef unsigned long long u64;

// ---------------- device scratch (no allocs allowed) ----------------
__device__ int g_is64;
__device__ int g_src[NE];
__device__ int g_dst[NE];
__device__ __align__(16) float g_hn [NN * 32];
__device__ __align__(16) float g_Ls [NN * 4];
__device__ __align__(16) float g_Ld [NN * 4];
__device__ __align__(16) float g_P1 [NN * 32];
__device__ __align__(16) float g_P2 [NN * 32];
__device__ __align__(16) float g_num[NN * 32];
__device__ __align__(16) float g_den[NN * 4];
__device__ __align__(16) float g_x1 [NN * 32];
__device__ __align__(16) float g_y1 [(size_t)NE * 32];

// ---------------- f32x2 packed-math helpers ----------------
__device__ __forceinline__ u64 pk2(float a) {
    u64 r; asm("mov.b64 %0, {%1, %1};" : "=l"(r) : "f"(a)); return r;
}
__device__ __forceinline__ u64 pkab(float a, float b) {
    u64 r; asm("mov.b64 %0, {%1, %2};" : "=l"(r) : "f"(a), "f"(b)); return r;
}
__device__ __forceinline__ void upk(u64 v, float& a, float& b) {
    asm("mov.b64 {%0, %1}, %2;" : "=f"(a), "=f"(b) : "l"(v));
}
__device__ __forceinline__ void fma2(u64& d, u64 a, u64 b) {
    asm("fma.rn.f32x2 %0, %1, %2, %0;" : "+l"(d) : "l"(a), "l"(b));
}

// global float reductions (L2-side, no return)
__device__ __forceinline__ void red1(float* p, float a) {
    asm volatile("red.global.add.f32 [%0], %1;" :: "l"(p), "f"(a) : "memory");
}
__device__ __forceinline__ void red4(float* p, float a, float b, float c, float d) {
    asm volatile("red.global.add.v4.f32 [%0], {%1, %2, %3, %4};"
                 :: "l"(p), "f"(a), "f"(b), "f"(c), "f"(d) : "memory");
}

// ---------------- index dtype detection + conversion (+zero accumulators) ----------------
__global__ void k_detect(const int* __restrict__ raw) {
    if (threadIdx.x == 0 && blockIdx.x == 0) {
        int s = 0;
#pragma unroll
        for (int i = 0; i < 64; i++) s |= raw[2 * i + 1];
        g_is64 = (s == 0) ? 1 : 0;
    }
}

__global__ void k_conv(const void* __restrict__ raw) {
    int e = blockIdx.x * blockDim.x + threadIdx.x;
    if (e >= NE) return;
    if (g_is64) {
        const long long* p = (const long long*)raw;
        g_src[e] = (int)p[e];
        g_dst[e] = (int)p[NE + e];
    } else {
        const int* p = (const int*)raw;
        g_src[e] = p[e];
        g_dst[e] = p[NE + e];
    }
    g_num[e] = 0.f;                 // NN*32 == NE
    if (e < NN * 4) g_den[e] = 0.f;
}

// ---------------- node-side precompute ----------------
template <int K, bool DOP, bool FROMX1>
__global__ void k_node_prep(const float* __restrict__ X,
                            const float* __restrict__ Wn, const float* __restrict__ bn,
                            const float* __restrict__ as_, const float* __restrict__ ad_,
                            const float* __restrict__ Weo) {
    int gw   = (blockIdx.x * blockDim.x + threadIdx.x) >> 5;
    int lane = threadIdx.x & 31;
    if (gw >= NN) return;
    const float* x = (FROMX1 ? (const float*)g_x1 : X) + (size_t)gw * K;
    float acc = bn[lane];
#pragma unroll 8
    for (int k = 0; k < K; k++)
        acc = fmaf(__ldg(x + k), Wn[k * 32 + lane], acc);
    g_hn[gw * 32 + lane] = acc;

    float ts = acc * as_[lane];
    float td = acc * ad_[lane];
#pragma unroll
    for (int off = 1; off < 8; off <<= 1) {
        ts += __shfl_xor_sync(0xffffffffu, ts, off);
        td += __shfl_xor_sync(0xffffffffu, td, off);
    }
    if ((lane & 7) == 0) {
        g_Ls[gw * 4 + (lane >> 3)] = ts;
        g_Ld[gw * 4 + (lane >> 3)] = td;
    }
    if (DOP) {
        __shared__ float sh[8][32];
        int w = threadIdx.x >> 5;
        sh[w][lane] = acc;
        __syncwarp();
        float p1 = 0.f, p2 = 0.f;
#pragma unroll 8
        for (int k = 0; k < 32; k++) {
            float v = sh[w][k];
            p1 = fmaf(v, Weo[k * 32 + lane],        p1);
            p2 = fmaf(v, Weo[(32 + k) * 32 + lane], p2);
        }
        g_P1[gw * 32 + lane] = p1;
        g_P2[gw * 32 + lane] = p2;
    }
}

// ---------------- edge kernel: 4 lanes per edge (lane = head, owns 8 channels) ----------------
// Block = 256 threads = 8 warps = 64 edges. Grid = NE/64 = 25000 (exact).
template <bool L1>
__global__ __launch_bounds__(256) void k_edge(
        const float* __restrict__ EF,          // layer1: edge feats; ignored for layer2
        const float* __restrict__ We, const float* __restrict__ be,
        const float* __restrict__ ae,
        const float* __restrict__ Weo, const float* __restrict__ beo) {
    __shared__ __align__(16) float sWe[1024];
    __shared__ __align__(16) float sW3[1024];
    __shared__ __align__(16) float sEF[8][8 * 36];   // 8 warps x 8 edges x (32+4 pad)

    int tid = threadIdx.x;
    ((float4*)sWe)[tid] = __ldg((const float4*)We + tid);
    if (L1) ((float4*)sW3)[tid] = __ldg((const float4*)(Weo + 2048) + tid);

    int wid  = tid >> 5, lane = tid & 31;
    int slot = lane >> 2;          // edge slot within warp (0..7)
    int h    = lane & 3;           // head (= this lane's channel block h*8..h*8+7)
    int e0   = blockIdx.x * 64 + wid * 8;
    int e    = e0 + slot;

    // stage 8 edge-feature rows (1KB) coalesced into padded smem
    const float* src_rows = L1 ? (EF + (size_t)e0 * 32) : (g_y1 + (size_t)e0 * 32);
    float* sef = sEF[wid];
#pragma unroll
    for (int t = 0; t < 2; t++) {
        int v = t * 32 + lane;                       // float4 index 0..63
        float4 d = __ldg((const float4*)src_rows + v);
        *(float4*)(sef + (v >> 3) * 36 + (v & 7) * 4) = d;
    }
    __syncthreads();

    int src = g_src[e], dst = g_dst[e];

    // this edge's 32 features -> registers (8x LDS.128, conflict-free across slots)
    float ef[32];
    {
        const float4* er = (const float4*)(sef + slot * 36);
#pragma unroll
        for (int i = 0; i < 8; i++) {
            float4 v = er[i];
            ef[4 * i] = v.x; ef[4 * i + 1] = v.y;
            ef[4 * i + 2] = v.z; ef[4 * i + 3] = v.w;
        }
    }

    // he[c] for c = h*8..h*8+7  (u64-packed pairs)
    u64 he[4];
    {
        float4 b0 = __ldg((const float4*)be + h * 2);
        float4 b1 = __ldg((const float4*)be + h * 2 + 1);
        he[0] = pkab(b0.x, b0.y); he[1] = pkab(b0.z, b0.w);
        he[2] = pkab(b1.x, b1.y); he[3] = pkab(b1.z, b1.w);
    }
#pragma unroll
    for (int k = 0; k < 32; k++) {
        u64 xx = pk2(ef[k]);
        const ulonglong2* wr = (const ulonglong2*)(sWe + k * 32) + h * 2;
        ulonglong2 wa = wr[0], wb = wr[1];            // one 128B row / warp / k
        fma2(he[0], wa.x, xx); fma2(he[1], wa.y, xx);
        fma2(he[2], wb.x, xx); fma2(he[3], wb.y, xx);
    }
    float he_f[8];
    upk(he[0], he_f[0], he_f[1]); upk(he[1], he_f[2], he_f[3]);
    upk(he[2], he_f[4], he_f[5]); upk(he[3], he_f[6], he_f[7]);

    // attention logit for this lane's head (no max-subtraction; fp32-range safe)
    float ex;
    {
        float4 a0 = __ldg((const float4*)ae + h * 2);
        float4 a1 = __ldg((const float4*)ae + h * 2 + 1);
        float le = he_f[0] * a0.x;
        le = fmaf(he_f[1], a0.y, le); le = fmaf(he_f[2], a0.z, le);
        le = fmaf(he_f[3], a0.w, le); le = fmaf(he_f[4], a1.x, le);
        le = fmaf(he_f[5], a1.y, le); le = fmaf(he_f[6], a1.z, le);
        le = fmaf(he_f[7], a1.w, le);
        float lg = __ldg(g_Ls + src * 4 + h) + __ldg(g_Ld + dst * 4 + h) + le;
        lg = lg > 0.f ? lg : 0.2f * lg;               // leaky_relu(0.2)
        ex = __expf(lg);
    }
    red1(&g_den[dst * 4 + h], ex);

    // messages: num[dst][h*8+c] += ex * (hn[src][c] + he[c])
    {
        const float4* hp = (const float4*)(g_hn + src * 32 + h * 8);
        float4 hs0 = __ldg(hp), hs1 = __ldg(hp + 1);
        red4(&g_num[dst * 32 + h * 8],
             ex * (hs0.x + he_f[0]), ex * (hs0.y + he_f[1]),
             ex * (hs0.z + he_f[2]), ex * (hs0.w + he_f[3]));
        red4(&g_num[dst * 32 + h * 8 + 4],
             ex * (hs1.x + he_f[4]), ex * (hs1.y + he_f[5]),
             ex * (hs1.z + he_f[6]), ex * (hs1.w + he_f[7]));
    }

    if (L1) {
        // q = he@W3 + P1[src] + P2[dst] + beo; y1 = softmax(q) over 32 channels
        u64 q[4];
        {
            float4 b0 = __ldg((const float4*)beo + h * 2);
            float4 b1 = __ldg((const float4*)beo + h * 2 + 1);
            q[0] = pkab(b0.x, b0.y); q[1] = pkab(b0.z, b0.w);
            q[2] = pkab(b1.x, b1.y); q[3] = pkab(b1.z, b1.w);
        }
#pragma unroll
        for (int k = 0; k < 32; k++) {
            float x = __shfl_sync(0xffffffffu, he_f[k & 7], k >> 3, 4); // he[k] from owning lane
            u64 xx = pk2(x);
            const ulonglong2* wr = (const ulonglong2*)(sW3 + k * 32) + h * 2;
            ulonglong2 wa = wr[0], wb = wr[1];
            fma2(q[0], wa.x, xx); fma2(q[1], wa.y, xx);
            fma2(q[2], wb.x, xx); fma2(q[3], wb.y, xx);
        }
        float qf[8];
        upk(q[0], qf[0], qf[1]); upk(q[1], qf[2], qf[3]);
        upk(q[2], qf[4], qf[5]); upk(q[3], qf[6], qf[7]);
        {
            const float4* p1p = (const float4*)(g_P1 + src * 32 + h * 8);
            const float4* p2p = (const float4*)(g_P2 + dst * 32 + h * 8);
            float4 a0 = __ldg(p1p), a1 = __ldg(p1p + 1);
            float4 b0 = __ldg(p2p), b1 = __ldg(p2p + 1);
            qf[0] += a0.x + b0.x; qf[1] += a0.y + b0.y;
            qf[2] += a0.z + b0.z; qf[3] += a0.w + b0.w;
            qf[4] += a1.x + b1.x; qf[5] += a1.y + b1.y;
            qf[6] += a1.z + b1.z; qf[7] += a1.w + b1.w;
        }
        float mx = qf[0];
#pragma unroll
        for (int j = 1; j < 8; j++) mx = fmaxf(mx, qf[j]);
        mx = fmaxf(mx, __shfl_xor_sync(0xffffffffu, mx, 1, 4));
        mx = fmaxf(mx, __shfl_xor_sync(0xffffffffu, mx, 2, 4));
        float s = 0.f;
#pragma unroll
        for (int j = 0; j < 8; j++) { qf[j] = __expf(qf[j] - mx); s += qf[j]; }
        s += __shfl_xor_sync(0xffffffffu, s, 1, 4);
        s += __shfl_xor_sync(0xffffffffu, s, 2, 4);
        float inv = 1.f / s;
        float4* yp = (float4*)(g_y1 + (size_t)e * 32 + h * 8);
        yp[0] = make_float4(qf[0] * inv, qf[1] * inv, qf[2] * inv, qf[3] * inv);
        yp[1] = make_float4(qf[4] * inv, qf[5] * inv, qf[6] * inv, qf[7] * inv);
    }
}

// ---------------- node finalize: layer 1 (divide + softmax), re-zero accumulators ----------------
__global__ void k_fin1() {
    int n = blockIdx.x * blockDim.x + threadIdx.x;
    if (n >= NN) return;
    float4 d4 = *((const float4*)g_den + n);
    *((float4*)g_den + n) = make_float4(0.f, 0.f, 0.f, 0.f);
    float den[4] = {d4.x, d4.y, d4.z, d4.w};
    float4* np = (float4*)g_num + n * 8;
    float v[32];
#pragma unroll
    for (int i = 0; i < 8; i++) {
        float4 a = np[i];
        np[i] = make_float4(0.f, 0.f, 0.f, 0.f);
        float id = 1.f / (den[i >> 1] + 1e-9f);
        v[4 * i] = a.x * id; v[4 * i + 1] = a.y * id;
        v[4 * i + 2] = a.z * id; v[4 * i + 3] = a.w * id;
    }
    float mx = -1e30f;
#pragma unroll
    for (int j = 0; j < 32; j++) mx = fmaxf(mx, v[j]);
    float s = 0.f;
#pragma unroll
    for (int j = 0; j < 32; j++) { v[j] = __expf(v[j] - mx); s += v[j]; }
    float inv = 1.f / s;
    float4* xp = (float4*)g_x1 + n * 8;
#pragma unroll
    for (int i = 0; i < 8; i++)
        xp[i] = make_float4(v[4 * i] * inv, v[4 * i + 1] * inv,
                            v[4 * i + 2] * inv, v[4 * i + 3] * inv);
}

// ---------------- node finalize: layer 2 (divide + relu) + linear head ----------------
__global__ void k_fin2(const float* __restrict__ Wl, const float* __restrict__ bl,
                       float* __restrict__ out) {
    int n = blockIdx.x * blockDim.x + threadIdx.x;
    if (n >= NN) return;
    float4 d4 = *((const float4*)g_den + n);
    float den[4] = {d4.x, d4.y, d4.z, d4.w};
    const float4* np = (const float4*)g_num + n * 8;
    float acc = bl[0];
#pragma unroll
    for (int i = 0; i < 8; i++) {
        float4 a = np[i];
        float id = 1.f / (den[i >> 1] + 1e-9f);
        acc = fmaf(fmaxf(a.x * id, 0.f), Wl[4 * i],     acc);
        acc = fmaf(fmaxf(a.y * id, 0.f), Wl[4 * i + 1], acc);
        acc = fmaf(fmaxf(a.z * id, 0.f), Wl[4 * i + 2], acc);
        acc = fmaf(fmaxf(a.w * id, 0.f), Wl[4 * i + 3], acc);
    }
    out[n] = acc;
}

// ---------------- launch ----------------
extern "C" void kernel_launch(void* const* d_in, const int* in_sizes, int n_in,
                              void* d_out, int out_size) {
    const float* nodeF = (const float*)d_in[0];
    const float* edgeF = (const float*)d_in[1];
    const void*  eidx  = d_in[2];
    const float *Wn1 = (const float*)d_in[3],  *bn1 = (const float*)d_in[4];
    const float *We1 = (const float*)d_in[5],  *be1 = (const float*)d_in[6];
    const float *as1 = (const float*)d_in[7],  *ad1 = (const float*)d_in[8];
    const float *ae1 = (const float*)d_in[9];
    const float *Weo1 = (const float*)d_in[10], *beo1 = (const float*)d_in[11];
    const float *Wn2 = (const float*)d_in[12], *bn2 = (const float*)d_in[13];
    const float *We2 = (const float*)d_in[14], *be2 = (const float*)d_in[15];
    const float *as2 = (const float*)d_in[16], *ad2 = (const float*)d_in[17];
    const float *ae2 = (const float*)d_in[18];
    // d_in[19]/d_in[20] (Weo2/beo2) are dead: layer-2 edge output is unused.
    const float *Wl = (const float*)d_in[21], *bl = (const float*)d_in[22];

    const int TB = 256;
    const int gC = (NE + TB - 1) / TB;           // 6250
    const int gE = NE / 64;                      // 25000 (exact: 64 edges/block)
    const int gW = (NN * 32 + TB - 1) / TB;      // warp-per-node kernels
    const int gN = (NN + TB - 1) / TB;

    k_detect<<<1, 32>>>((const int*)eidx);
    k_conv<<<gC, TB>>>(eidx);

    // ---- layer 1 ----
    k_node_prep<128, true, false><<<gW, TB>>>(nodeF, Wn1, bn1, as1, ad1, Weo1);
    k_edge<true><<<gE, TB>>>(edgeF, We1, be1, ae1, Weo1, beo1);
    k_fin1<<<gN, TB>>>();                        // also re-zeros num/den

    // ---- layer 2 ----
    k_node_prep<32, false, true><<<gW, TB>>>(nullptr, Wn2, bn2, as2, ad2, Weo1 /*unused*/);
    k_edge<false><<<gE, TB>>>(nullptr, We2, be2, ae2, nullptr, nullptr);
    k_fin2<<<gN, TB>>>(Wl, bl, (float*)d_out);
}